// round 15
// baseline (speedup 1.0000x reference)
#include <cuda_runtime.h>
#include <math.h>

#define BB 128
#define TT 25
#define VOCAB 10000
#define EMBD 512
#define VGGD 4096
#define HIDD 512
#define GBLK 256
#define THR  256

typedef unsigned long long u64;

// ---------------- packed f32x2 helpers (FFMA2: 2 MACs / instr) ---------------
__device__ __forceinline__ u64 pack2(float v) {
    u64 r; unsigned b = __float_as_uint(v);
    asm("mov.b64 %0, {%1, %1};" : "=l"(r) : "r"(b));
    return r;
}
__device__ __forceinline__ void fma2(u64& d, u64 a, u64 b) {
    asm("fma.rn.f32x2 %0, %1, %2, %0;" : "+l"(d) : "l"(a), "l"(b));
}
__device__ __forceinline__ float2 unpack2(u64 v) {
    unsigned lo, hi;
    asm("mov.b64 {%0, %1}, %2;" : "=r"(lo), "=r"(hi) : "l"(v));
    return make_float2(__uint_as_float(lo), __uint_as_float(hi));
}
__device__ __forceinline__ float fsel(const float4& a, int kk) {
    return kk == 0 ? a.x : kk == 1 ? a.y : kk == 2 ? a.z : a.w;
}

// ---------------- scratch (device globals; no allocation allowed) ------------
__device__ float g_h0[BB * HIDD];
__device__ float g_E[TT * BB * EMBD];
__device__ float g_X0[TT * BB * 3 * HIDD];     // [u|r|c] per row
__device__ float g_S1[TT * BB * HIDD];
__device__ float g_s0buf[2][BB * HIDD];
__device__ float g_gu0[BB * HIDD];
__device__ float g_gr0[BB * HIDD];
__device__ float g_gu1[BB * HIDD];
__device__ float g_gr1[BB * HIDD];
__device__ float g_W0top[HIDD * 3 * HIDD];
__device__ float g_b0top[3 * HIDD];
__device__ unsigned g_bar_count;
__device__ unsigned g_bar_sense;

// ---------------- pack layer-0 top weights -----------------------------------
__global__ void pack_w0top(const float* __restrict__ Wu0, const float* __restrict__ Wr0,
                           const float* __restrict__ Wc0, const float* __restrict__ bu0,
                           const float* __restrict__ br0, const float* __restrict__ bc0) {
    int idx = blockIdx.x * blockDim.x + threadIdx.x;
    const int total = HIDD * 3 * HIDD;
    if (idx < total) {
        int k = idx / (3 * HIDD);
        int j = idx - k * (3 * HIDD);
        float v;
        if (j < HIDD)           v = Wu0[k * HIDD + j];
        else if (j < 2 * HIDD)  v = Wr0[k * HIDD + (j - HIDD)];
        else                    v = Wc0[k * HIDD + (j - 2 * HIDD)];
        g_W0top[idx] = v;
    }
    if (idx < 3 * HIDD) {
        g_b0top[idx] = (idx < HIDD) ? bu0[idx]
                     : (idx < 2 * HIDD) ? br0[idx - HIDD]
                                        : bc0[idx - 2 * HIDD];
    }
}

// ---------------- embedding gather -------------------------------------------
__global__ void embed_gather(const float* __restrict__ emb, const int* __restrict__ tokens) {
    int r = blockIdx.x;
    int t = r / BB;
    int b = r - t * BB;
    int tok = tokens[b * TT + t];
    const float4* src = (const float4*)(emb + (size_t)tok * EMBD);
    float4* dst = (float4*)(g_E + (size_t)r * EMBD);
    dst[threadIdx.x] = src[threadIdx.x];
}

// ---------------- big tiled SGEMM: C = A@W + bias (FFMA2 core) ---------------
template <int AREMAP>
__global__ __launch_bounds__(256) void sgemm_big(
    const float* __restrict__ A, const float* __restrict__ W,
    const float* __restrict__ bias, float* __restrict__ C,
    int M, int N, int K)
{
    __shared__ float As[8][128];
    __shared__ float Ws[8][128];
    int tid = threadIdx.x;
    int m0 = blockIdx.y * 128;
    int n0 = blockIdx.x * 128;
    int tx = tid & 15;
    int ty = tid >> 4;

    u64 acc2[8][4];
#pragma unroll
    for (int i = 0; i < 8; i++)
#pragma unroll
        for (int j = 0; j < 4; j++) acc2[i][j] = 0ull;

    int lar = tid >> 1;
    int lak = (tid & 1) * 4;
    int arow = m0 + lar;
    if (AREMAP) arow = (arow % TT) * BB + (arow / TT);
    const float* Aptr = A + (size_t)arow * K;
    int lwk = tid >> 5;
    int lwc = (tid & 31) * 4;

    for (int k0 = 0; k0 < K; k0 += 8) {
        float4 av = *(const float4*)(Aptr + k0 + lak);
        As[lak + 0][lar] = av.x;
        As[lak + 1][lar] = av.y;
        As[lak + 2][lar] = av.z;
        As[lak + 3][lar] = av.w;

        int wn = n0 + lwc;
        const float* Wp = W + (size_t)(k0 + lwk) * N + wn;
        float4 wv;
        if (wn + 3 < N) {
            wv = *(const float4*)Wp;
        } else {
            wv.x = (wn + 0 < N) ? Wp[0] : 0.f;
            wv.y = (wn + 1 < N) ? Wp[1] : 0.f;
            wv.z = (wn + 2 < N) ? Wp[2] : 0.f;
            wv.w = (wn + 3 < N) ? Wp[3] : 0.f;
        }
        *(float4*)&Ws[lwk][lwc] = wv;
        __syncthreads();

#pragma unroll
        for (int kk = 0; kk < 8; kk++) {
            float4 a0 = *(const float4*)&As[kk][ty * 4];
            float4 a1 = *(const float4*)&As[kk][64 + ty * 4];
            float4 w0 = *(const float4*)&Ws[kk][tx * 4];
            float4 w1 = *(const float4*)&Ws[kk][64 + tx * 4];
            u64 wv2[4];
            wv2[0] = ((const u64*)&w0)[0]; wv2[1] = ((const u64*)&w0)[1];
            wv2[2] = ((const u64*)&w1)[0]; wv2[3] = ((const u64*)&w1)[1];
            float ar[8] = {a0.x, a0.y, a0.z, a0.w, a1.x, a1.y, a1.z, a1.w};
#pragma unroll
            for (int i = 0; i < 8; i++) {
                u64 pa = pack2(ar[i]);
                fma2(acc2[i][0], pa, wv2[0]);
                fma2(acc2[i][1], pa, wv2[1]);
                fma2(acc2[i][2], pa, wv2[2]);
                fma2(acc2[i][3], pa, wv2[3]);
            }
        }
        __syncthreads();
    }

#pragma unroll
    for (int i = 0; i < 8; i++) {
        int row = m0 + ((i < 4) ? (ty * 4 + i) : (64 + ty * 4 + i - 4));
        float* Crow = C + (size_t)row * N;
#pragma unroll
        for (int j = 0; j < 4; j++) {
            float2 v = unpack2(acc2[i][j]);
            int col = n0 + ((j < 2) ? (tx * 4 + j * 2) : (64 + tx * 4 + (j - 2) * 2));
            if (col < N)     Crow[col]     = v.x + bias[col];
            if (col + 1 < N) Crow[col + 1] = v.y + bias[col + 1];
        }
    }
}

// ================== persistent recurrence kernel =============================
struct RP {
    const float* vgg;
    const float* W_in; const float* b_in;
    const float* Wu0; const float* Wr0; const float* Wc0;
    const float* Wu1; const float* Wr1; const float* Wc1;
    const float* bu1; const float* br1; const float* bc1;
};

__device__ __forceinline__ void gridbar(int tid, unsigned* ps) {
    __threadfence();
    __syncthreads();
    if (tid == 0) {
        unsigned ns = *ps ^ 1u;
        *ps = ns;
        if (atomicAdd(&g_bar_count, 1u) == GBLK - 1) {
            *(volatile unsigned*)&g_bar_count = 0;
            __threadfence();
            *(volatile unsigned*)&g_bar_sense = ns;
        } else {
            while (*(volatile unsigned*)&g_bar_sense != ns) { }
        }
        __threadfence();
    }
    __syncthreads();
}

// ---- stage one 64-k A chunk [128 rows] into smem (coalesced, optional ⊙) ----
__device__ __forceinline__ void stageA(float* dst, const float* __restrict__ s1,
                                       int str1, const float* __restrict__ s2,
                                       int kbase, int tid) {
#pragma unroll
    for (int i = 0; i < 8; i++) {
        int lin = tid + i * THR;
        int row = lin >> 4, f4i = (lin & 15) * 4;
        float4 v = __ldcg((const float4*)(s1 + (size_t)row * str1 + kbase + f4i));
        if (s2) {
            float4 b = __ldcg((const float4*)(s2 + (size_t)row * HIDD + kbase + f4i));
            v.x *= b.x; v.y *= b.y; v.z *= b.z; v.w *= b.w;
        }
        *(float4*)(dst + row * 68 + f4i) = v;
    }
}

// ---- single gate accumulate: R=4 rows, C=4 cols, this warp's 8k slice -------
__device__ __forceinline__ void gAcc4(u64 (&g)[4][2], const float* sA,
                                      const float* sW, int l, int kq) {
#pragma unroll
    for (int kb = 0; kb < 8; kb += 4) {
        int k0 = kq * 8 + kb;
        float4 a[4];
#pragma unroll
        for (int i = 0; i < 4; i++) a[i] = *(const float4*)(sA + (l + 32 * i) * 68 + k0);
#pragma unroll
        for (int kk = 0; kk < 4; kk++) {
            float4 wv = *(const float4*)(sW + (k0 + kk) * 4);
            u64 w0 = ((const u64*)&wv)[0], w1 = ((const u64*)&wv)[1];
#pragma unroll
            for (int i = 0; i < 4; i++) {
                u64 pa = pack2(fsel(a[i], kk));
                fma2(g[i][0], pa, w0); fma2(g[i][1], pa, w1);
            }
        }
    }
}

// ---- candidate accumulate: R=4 rows, C=2 cols -------------------------------
__device__ __forceinline__ void cAcc2(u64 (&c)[4], const float* sA,
                                      const float* sW, int l, int kq) {
#pragma unroll
    for (int kb = 0; kb < 8; kb += 4) {
        int k0 = kq * 8 + kb;
        float4 a[4];
#pragma unroll
        for (int i = 0; i < 4; i++) a[i] = *(const float4*)(sA + (l + 32 * i) * 68 + k0);
#pragma unroll
        for (int kk = 0; kk < 4; kk++) {
            u64 wv = *(const u64*)(sW + (k0 + kk) * 2);
#pragma unroll
            for (int i = 0; i < 4; i++) {
                u64 pa = pack2(fsel(a[i], kk));
                fma2(c[i], pa, wv);
            }
        }
    }
}

// ---- fused PhA accumulate: g1 (both K halves), c1-top, optional g0 ----------
__device__ __forceinline__ void phaAcc(u64 (&g1)[4][2], u64 (&g0)[4][2], u64 (&c1)[4],
    const float* sA0v, const float* sA1v,
    const float* wg1a, const float* wg1b, const float* wg0, const float* wc1,
    int l, int kq, bool dog0)
{
#pragma unroll
    for (int kb = 0; kb < 8; kb += 4) {
        int k0 = kq * 8 + kb;
        float4 a0[4], a1[4];
#pragma unroll
        for (int i = 0; i < 4; i++) {
            a0[i] = *(const float4*)(sA0v + (l + 32 * i) * 68 + k0);
            a1[i] = *(const float4*)(sA1v + (l + 32 * i) * 68 + k0);
        }
#pragma unroll
        for (int kk = 0; kk < 4; kk++) {
            float4 wa = *(const float4*)(wg1a + (k0 + kk) * 4);
            float4 wb = *(const float4*)(wg1b + (k0 + kk) * 4);
            float4 w0v = *(const float4*)(wg0 + (k0 + kk) * 4);
            u64 wc = *(const u64*)(wc1 + (k0 + kk) * 2);
#pragma unroll
            for (int i = 0; i < 4; i++) {
                u64 p0 = pack2(fsel(a0[i], kk));
                u64 p1 = pack2(fsel(a1[i], kk));
                fma2(g1[i][0], p0, ((const u64*)&wa)[0]);
                fma2(g1[i][1], p0, ((const u64*)&wa)[1]);
                fma2(g1[i][0], p1, ((const u64*)&wb)[0]);
                fma2(g1[i][1], p1, ((const u64*)&wb)[1]);
                if (dog0) {
                    fma2(g0[i][0], p0, ((const u64*)&w0v)[0]);
                    fma2(g0[i][1], p0, ((const u64*)&w0v)[1]);
                }
                fma2(c1[i], p0, wc);
            }
        }
    }
}

// ---- PhB accumulate: c1-bottom + optional c0 --------------------------------
__device__ __forceinline__ void phbAcc(u64 (&c1)[4], u64 (&c0)[4],
    const float* sA0v, const float* sA1v,
    const float* wc1b, const float* wc0w, int l, int kq, bool doc0)
{
#pragma unroll
    for (int kb = 0; kb < 8; kb += 4) {
        int k0 = kq * 8 + kb;
        float4 a0[4], a1[4];
#pragma unroll
        for (int i = 0; i < 4; i++) {
            a0[i] = *(const float4*)(sA0v + (l + 32 * i) * 68 + k0);
            if (doc0) a1[i] = *(const float4*)(sA1v + (l + 32 * i) * 68 + k0);
        }
#pragma unroll
        for (int kk = 0; kk < 4; kk++) {
            u64 w1 = *(const u64*)(wc1b + (k0 + kk) * 2);
            u64 w0 = *(const u64*)(wc0w + (k0 + kk) * 2);
#pragma unroll
            for (int i = 0; i < 4; i++) {
                u64 p0 = pack2(fsel(a0[i], kk));
                fma2(c1[i], p0, w1);
                if (doc0) {
                    u64 p1 = pack2(fsel(a1[i], kk));
                    fma2(c0[i], p1, w0);
                }
            }
        }
    }
}

// ---- 8-warp k-slice tree reduction (3 rounds) -------------------------------
template <int NF, int STR>
__device__ __forceinline__ void redq8(float* v, float* buf, int l, int w) {
#pragma unroll 1
    for (int h = 4; h >= 1; h >>= 1) {
        __syncthreads();
        if (w >= h && w < 2 * h) {
            float* b = buf + ((w - h) * 32 + l) * STR;
#pragma unroll
            for (int j = 0; j < NF; j += 4)
                *(float4*)(b + j) = make_float4(v[j], v[j + 1], v[j + 2], v[j + 3]);
        }
        __syncthreads();
        if (w < h) {
            const float* b = buf + (w * 32 + l) * STR;
#pragma unroll
            for (int j = 0; j < NF; j++) v[j] += b[j];
        }
    }
}

__device__ __forceinline__ void unpG4(const u64 (&a)[4][2], float (&v)[16]) {
#pragma unroll
    for (int i = 0; i < 4; i++)
#pragma unroll
        for (int c = 0; c < 2; c++) {
            float2 p = unpack2(a[i][c]);
            v[i * 4 + 2 * c] = p.x; v[i * 4 + 2 * c + 1] = p.y;
        }
}
__device__ __forceinline__ void unpC2(const u64 (&a)[4], float (&v)[8]) {
#pragma unroll
    for (int i = 0; i < 4; i++) {
        float2 p = unpack2(a[i]);
        v[i * 2] = p.x; v[i * 2 + 1] = p.y;
    }
}

__device__ __forceinline__ float sigm(float x) { return 1.f / (1.f + expf(-x)); }

// smem layout (floats)
#define SM_WG1   0        // 1024 x 4
#define SM_WG0   4096     // 512 x 4
#define SM_WC1T  6144     // 512 x 2
#define SM_WC1B  7168     // 512 x 2
#define SM_WC0B  8192     // 512 x 2
#define SM_SA0   9216     // 128 x 68
#define SM_SA1   17920    // 128 x 68
#define SM_TOTALF 26624   // 104 KB

__global__ __launch_bounds__(THR, 2) void recur_kernel(RP p) {
    extern __shared__ float sm[];
    float* sWg1  = sm + SM_WG1;
    float* sWg0  = sm + SM_WG0;
    float* sWc1t = sm + SM_WC1T;
    float* sWc1b = sm + SM_WC1B;
    float* sWc0b = sm + SM_WC0B;
    float* sA0   = sm + SM_SA0;
    float* sA1   = sm + SM_SA1;
    float* sred  = sm + SM_SA0;   // alias: used only after chunk loops
    __shared__ unsigned s_sense;

    int tid = threadIdx.x, bid = blockIdx.x;
    if (tid == 0) s_sense = *(volatile unsigned*)&g_bar_sense;

    const int l = tid & 31;
    const int w = tid >> 5;              // k-slice 0..7
    const int c0g  = bid * 4;            // gate cols [c0g, c0g+4) of 1024
    const int half = c0g >= HIDD;
    const int wcol = c0g & (HIDD - 1);
    const int cc   = bid * 2;            // candidate cols [cc, cc+2) of 512

    // ---- stage all weight slices once (persist whole kernel) -------------
    {
        const float* Wg1 = half ? p.Wr1 : p.Wu1;
        for (int r = tid; r < 1024; r += THR)
            *(float4*)(sWg1 + r * 4) = __ldg((const float4*)(Wg1 + (size_t)r * HIDD + wcol));
        const float* Wg0 = (half ? p.Wr0 : p.Wu0) + HIDD * HIDD;
        for (int r = tid; r < 512; r += THR) {
            *(float4*)(sWg0 + r * 4) = __ldg((const float4*)(Wg0 + (size_t)r * HIDD + wcol));
            *(float2*)(sWc1t + r * 2) = __ldg((const float2*)(p.Wc1 + (size_t)r * HIDD + cc));
            *(float2*)(sWc1b + r * 2) = __ldg((const float2*)(p.Wc1 + (size_t)(HIDD + r) * HIDD + cc));
            *(float2*)(sWc0b + r * 2) = __ldg((const float2*)(p.Wc0 + (size_t)(HIDD + r) * HIDD + cc));
        }
    }
    __syncthreads();

    // ---- h0 = tanh(vgg @ W_in + b_in): blocks 0..127, 4 cols each --------
    if (bid < 128) {
        const int ch0 = bid * 4;
        u64 H[4][2] = {};
#pragma unroll 1
        for (int ch = 0; ch < 64; ch++) {
            stageA(sA0, p.vgg, VGGD, nullptr, ch * 64, tid);
            __syncthreads();
#pragma unroll
            for (int kb = 0; kb < 8; kb += 4) {
                int k0 = w * 8 + kb;
                float4 a[4];
#pragma unroll
                for (int i = 0; i < 4; i++)
                    a[i] = *(const float4*)(sA0 + (l + 32 * i) * 68 + k0);
#pragma unroll
                for (int kk = 0; kk < 4; kk++) {
                    int kg = ch * 64 + k0 + kk;
                    float4 wv = __ldg((const float4*)(p.W_in + (size_t)kg * HIDD + ch0));
                    u64 w0 = ((const u64*)&wv)[0], w1 = ((const u64*)&wv)[1];
#pragma unroll
                    for (int i = 0; i < 4; i++) {
                        u64 pa = pack2(fsel(a[i], kk));
                        fma2(H[i][0], pa, w0); fma2(H[i][1], pa, w1);
                    }
                }
            }
            __syncthreads();
        }
        float v[16]; unpG4(H, v);
        redq8<16, 20>(v, sred, l, w);
        if (w == 0) {
            float4 bv = __ldg((const float4*)(p.b_in + ch0));
#pragma unroll
            for (int i = 0; i < 4; i++) {
                int row = l + 32 * i;
                float4 o = make_float4(tanhf(v[i * 4 + 0] + bv.x), tanhf(v[i * 4 + 1] + bv.y),
                                       tanhf(v[i * 4 + 2] + bv.z), tanhf(v[i * 4 + 3] + bv.w));
                *(float4*)(g_h0 + row * HIDD + ch0) = o;
            }
        }
    }
    gridbar(tid, &s_sense);

    // ---- prologue 1: gates0(0) from h0 -----------------------------------
    {
        u64 G[4][2] = {};
        for (int ch = 0; ch < 8; ch++) {
            stageA(sA0, g_h0, HIDD, nullptr, ch * 64, tid);
            __syncthreads();
            gAcc4(G, sA0, sWg0 + ch * 64 * 4, l, w);
            __syncthreads();
        }
        float v[16]; unpG4(G, v);
        redq8<16, 20>(v, sred, l, w);
        if (w == 0) {
            float* out = half ? g_gr0 : g_gu0;
#pragma unroll
            for (int i = 0; i < 4; i++) {
                int row = l + 32 * i;
                float4 xv = __ldcg((const float4*)(g_X0 + (size_t)row * 3 * HIDD + c0g));
                float4 o = make_float4(sigm(v[i * 4 + 0] + xv.x), sigm(v[i * 4 + 1] + xv.y),
                                       sigm(v[i * 4 + 2] + xv.z), sigm(v[i * 4 + 3] + xv.w));
                *(float4*)(out + row * HIDD + wcol) = o;
            }
        }
    }
    gridbar(tid, &s_sense);

    // ---- prologue 2: s0cur(0) --------------------------------------------
    {
        u64 C0[4] = {};
        for (int ch = 0; ch < 8; ch++) {
            stageA(sA0, g_gr0, HIDD, g_h0, ch * 64, tid);
            __syncthreads();
            cAcc2(C0, sA0, sWc0b + ch * 64 * 2, l, w);
            __syncthreads();
        }
        float v[8]; unpC2(C0, v);
        redq8<8, 12>(v, sred, l, w);
        if (w == 0) {
#pragma unroll
            for (int i = 0; i < 4; i++) {
                int row = l + 32 * i;
                float2 xv = __ldcg((const float2*)(g_X0 + (size_t)row * 3 * HIDD + 2 * HIDD + cc));
                float2 gu = __ldcg((const float2*)(g_gu0 + row * HIDD + cc));
                float2 hp = __ldcg((const float2*)(g_h0 + row * HIDD + cc));
                float ca = tanhf(v[i * 2 + 0] + xv.x);
                float cb = tanhf(v[i * 2 + 1] + xv.y);
                float2 o = make_float2(gu.x * hp.x + (1.f - gu.x) * ca,
                                       gu.y * hp.y + (1.f - gu.y) * cb);
                *(float2*)(&g_s0buf[0][row * HIDD + cc]) = o;
            }
        }
    }
    gridbar(tid, &s_sense);

    // ---- main loop: 2 barriers / step ------------------------------------
#pragma unroll 1
    for (int t = 0; t < TT; t++) {
        const float* s0c = g_s0buf[t & 1];
        const float* s1p = t ? (g_S1 + (size_t)(t - 1) * BB * HIDD) : g_h0;
        const float* X0n = g_X0 + (size_t)(t + 1) * BB * 3 * HIDD;
        const bool last = (t == TT - 1);

        u64 aC1[4] = {};

        // ===== PhA: gates1(t) + c1-top(t) + gates0(t+1) =====
        {
            u64 aG1[4][2] = {};
            u64 aG0[4][2] = {};
            for (int ch = 0; ch < 8; ch++) {
                stageA(sA0, s0c, HIDD, nullptr, ch * 64, tid);
                stageA(sA1, s1p, HIDD, nullptr, ch * 64, tid);
                __syncthreads();
                phaAcc(aG1, aG0, aC1, sA0, sA1,
                       sWg1 + ch * 64 * 4, sWg1 + (512 + ch * 64) * 4,
                       sWg0 + ch * 64 * 4, sWc1t + ch * 64 * 2, l, w, !last);
                __syncthreads();
            }
            float v1[16]; unpG4(aG1, v1);
            redq8<16, 20>(v1, sred, l, w);
            if (w == 0) {
                float4 bv = __ldg((const float4*)((half ? p.br1 : p.bu1) + wcol));
                float* out = half ? g_gr1 : g_gu1;
#pragma unroll
                for (int i = 0; i < 4; i++) {
                    int row = l + 32 * i;
                    float4 o = make_float4(sigm(v1[i * 4 + 0] + bv.x), sigm(v1[i * 4 + 1] + bv.y),
                                           sigm(v1[i * 4 + 2] + bv.z), sigm(v1[i * 4 + 3] + bv.w));
                    *(float4*)(out + row * HIDD + wcol) = o;
                }
            }
            if (!last) {
                float v0[16]; unpG4(aG0, v0);
                redq8<16, 20>(v0, sred, l, w);
                if (w == 0) {
                    float* out = half ? g_gr0 : g_gu0;
#pragma unroll
                    for (int i = 0; i < 4; i++) {
                        int row = l + 32 * i;
                        float4 xv = __ldcg((const float4*)(X0n + (size_t)row * 3 * HIDD + c0g));
                        float4 o = make_float4(sigm(v0[i * 4 + 0] + xv.x), sigm(v0[i * 4 + 1] + xv.y),
                                               sigm(v0[i * 4 + 2] + xv.z), sigm(v0[i * 4 + 3] + xv.w));
                        *(float4*)(out + row * HIDD + wcol) = o;
                    }
                }
            }
        }
        gridbar(tid, &s_sense);

        // ===== PhB: s1cur(t) + s0cur(t+1) =====
        {
            u64 aC0[4] = {};
            for (int ch = 0; ch < 8; ch++) {
                stageA(sA0, g_gr1, HIDD, s1p, ch * 64, tid);
                if (!last) stageA(sA1, g_gr0, HIDD, s0c, ch * 64, tid);
                __syncthreads();
                phbAcc(aC1, aC0, sA0, sA1,
                       sWc1b + ch * 64 * 2, sWc0b + ch * 64 * 2, l, w, !last);
                __syncthreads();
            }
            float vc[8]; unpC2(aC1, vc);
            redq8<8, 12>(vc, sred, l, w);
            if (w == 0) {
                float2 bc = __ldg((const float2*)(p.bc1 + cc));
                float* s1cur = g_S1 + (size_t)t * BB * HIDD;
#pragma unroll
                for (int i = 0; i < 4; i++) {
                    int row = l + 32 * i;
                    float2 gu = __ldcg((const float2*)(g_gu1 + row * HIDD + cc));
                    float2 hp = __ldcg((const float2*)(s1p + row * HIDD + cc));
                    float ca = tanhf(vc[i * 2 + 0] + bc.x);
                    float cb = tanhf(vc[i * 2 + 1] + bc.y);
                    float2 o = make_float2(gu.x * hp.x + (1.f - gu.x) * ca,
                                           gu.y * hp.y + (1.f - gu.y) * cb);
                    *(float2*)(s1cur + row * HIDD + cc) = o;
                }
            }
            if (!last) {
                float v0[8]; unpC2(aC0, v0);
                redq8<8, 12>(v0, sred, l, w);
                if (w == 0) {
                    float* s0n = g_s0buf[(t + 1) & 1];
#pragma unroll
                    for (int i = 0; i < 4; i++) {
                        int row = l + 32 * i;
                        float2 xv = __ldcg((const float2*)(X0n + (size_t)row * 3 * HIDD + 2 * HIDD + cc));
                        float2 gu = __ldcg((const float2*)(g_gu0 + row * HIDD + cc));
                        float2 hp = __ldcg((const float2*)(s0c + row * HIDD + cc));
                        float ca = tanhf(v0[i * 2 + 0] + xv.x);
                        float cb = tanhf(v0[i * 2 + 1] + xv.y);
                        float2 o = make_float2(gu.x * hp.x + (1.f - gu.x) * ca,
                                               gu.y * hp.y + (1.f - gu.y) * cb);
                        *(float2*)(s0n + row * HIDD + cc) = o;
                    }
                }
            }
        }
        gridbar(tid, &s_sense);
    }
}

// ---------------- final state write ------------------------------------------
__global__ void write_state(float* __restrict__ out) {
    int idx = blockIdx.x * blockDim.x + threadIdx.x;
    if (idx < BB * HIDD) {
        size_t base = (size_t)BB * TT * VOCAB;
        out[base + idx] = g_s0buf[(TT - 1) & 1][idx];
        out[base + BB * HIDD + idx] = g_S1[(size_t)(TT - 1) * BB * HIDD + idx];
    }
}

// ---------------- host driver -------------------------------------------------
template <typename Sym>
static float* sym(Sym& s) {
    void* p = nullptr;
    cudaGetSymbolAddress(&p, s);
    return (float*)p;
}

extern "C" void kernel_launch(void* const* d_in, const int* in_sizes, int n_in,
                              void* d_out, int out_size) {
    const float* vgg     = (const float*)d_in[0];
    const int*   xTokens = (const int*)d_in[1];
    int i = 2;
    if (n_in >= 20 && in_sizes[2] == 1) i = 3;   // skip is_train scalar
    const float* emb   = (const float*)d_in[i++];
    const float* W_in  = (const float*)d_in[i++];
    const float* b_in  = (const float*)d_in[i++];
    const float* Wu0   = (const float*)d_in[i++];
    const float* bu0   = (const float*)d_in[i++];
    const float* Wr0   = (const float*)d_in[i++];
    const float* br0   = (const float*)d_in[i++];
    const float* Wc0   = (const float*)d_in[i++];
    const float* bc0   = (const float*)d_in[i++];
    const float* Wu1   = (const float*)d_in[i++];
    const float* bu1   = (const float*)d_in[i++];
    const float* Wr1   = (const float*)d_in[i++];
    const float* br1   = (const float*)d_in[i++];
    const float* Wc1   = (const float*)d_in[i++];
    const float* bc1   = (const float*)d_in[i++];
    const float* W_out = (const float*)d_in[i++];
    const float* b_out = (const float*)d_in[i++];
    float* out = (float*)d_out;

    float* pE     = sym(g_E);
    float* pX0    = sym(g_X0);
    float* pS1    = sym(g_S1);
    float* pW0top = sym(g_W0top);
    float* pB0top = sym(g_b0top);

    // 1) pack layer-0 top weights + biases
    pack_w0top<<<(HIDD * 3 * HIDD + 255) / 256, 256>>>(Wu0, Wr0, Wc0, bu0, br0, bc0);

    // 2) embedding gather
    embed_gather<<<TT * BB, 128>>>(emb, xTokens);

    // 3) X0 = E_all @ W0top + b0top   [3200,512]@[512,1536]
    sgemm_big<0><<<dim3(3 * HIDD / 128, TT * BB / 128), 256>>>(
        pE, pW0top, pB0top, pX0, TT * BB, 3 * HIDD, HIDD);

    // 4) persistent recurrence (h0 + 25 GRU steps; 256 blocks, 2/SM)
    {
        static int smem_set = 0;
        if (!smem_set) {
            cudaFuncSetAttribute(recur_kernel,
                                 cudaFuncAttributeMaxDynamicSharedMemorySize,
                                 SM_TOTALF * 4);
            smem_set = 1;
        }
        RP rp;
        rp.vgg = vgg; rp.W_in = W_in; rp.b_in = b_in;
        rp.Wu0 = Wu0; rp.Wr0 = Wr0; rp.Wc0 = Wc0;
        rp.Wu1 = Wu1; rp.Wr1 = Wr1; rp.Wc1 = Wc1;
        rp.bu1 = bu1; rp.br1 = br1; rp.bc1 = bc1;
        recur_kernel<<<GBLK, THR, SM_TOTALF * 4>>>(rp);
    }

    // 5) logits = S1 @ W_out + b_out, output rows in (b*T+t) order via A-remap
    sgemm_big<1><<<dim3((VOCAB + 127) / 128, TT * BB / 128), 256>>>(
        pS1, W_out, b_out, out, TT * BB, VOCAB, HIDD);

    // 6) final state [2, B, HID]
    write_state<<<(BB * HIDD + 255) / 256, 256>>>(out);
}